// round 6
// baseline (speedup 1.0000x reference)
#include <cuda_runtime.h>
#include <cuda_bf16.h>

// GCN 2-layer: N=50000 nodes, E=800000 edges, feats 128 -> 64 -> 32.
// out[d] = relu( dinv[d] * (sum_{e: dst=d} g[src_e] + g[d]) + b )
// where g = dinv ⊙ (x @ W).
// edge_index dtype (int32 vs int64) is sniffed at runtime on device.

#define NMAX 50000
#define F1 64
#define F2 32

__device__ __align__(16) float d_deg [NMAX];
__device__ __align__(16) float d_dinv[NMAX];
__device__ __align__(16) float d_g1  [NMAX * F1];
__device__ __align__(16) float d_acc1[NMAX * F1];
__device__ __align__(16) float d_g2  [NMAX * F2];
__device__ __align__(16) float d_acc2[NMAX * F2];
__device__ int d_is64;

// ---------------------------------------------------------------------------
// Sniff edge_index dtype: int64 values < 2^31 have zero high halves at every
// odd 32-bit word; int32 random node ids in [0,50000) do not (P≈0).
__global__ void sniff_kernel(const void* ei) {
    if (threadIdx.x == 0 && blockIdx.x == 0) {
        const unsigned* w = (const unsigned*)ei;
        int all_zero = 1;
        for (int i = 0; i < 64; i++)
            if (w[2 * i + 1] != 0u) { all_zero = 0; break; }
        d_is64 = all_zero;
    }
}

__device__ __forceinline__ int edge_at(const void* ei, long long i, int n) {
    int v = d_is64 ? (int)((const long long*)ei)[i] : ((const int*)ei)[i];
    // defensive clamp: never produce a wild atomic address
    return min(max(v, 0), n - 1);
}

// ---------------------------------------------------------------------------
__global__ void deg_init_kernel(int n) {
    int i = blockIdx.x * blockDim.x + threadIdx.x;
    if (i < n) d_deg[i] = 1.0f;   // self-loop
}

__global__ void deg_count_kernel(const void* __restrict__ ei, int E, int n) {
    int e = blockIdx.x * blockDim.x + threadIdx.x;
    if (e < E) atomicAdd(&d_deg[edge_at(ei, (long long)E + e, n)], 1.0f);
}

__global__ void dinv_kernel(int n) {
    int i = blockIdx.x * blockDim.x + threadIdx.x;
    if (i < n) d_dinv[i] = rsqrtf(d_deg[i]);
}

// ---------------------------------------------------------------------------
// GEMM1: g1[i][j] = dinv[i] * sum_k x[i][k] * W1[k][j]   (K=128, COLS=64)
// Also writes acc1 = g1 (self-loop init).
__global__ __launch_bounds__(256) void gemm1_kernel(
    const float* __restrict__ x, const float* __restrict__ W, int n)
{
    __shared__ __align__(16) float Ws[128][64];   // 32 KB
    __shared__ __align__(16) float Xs[32][128];   // 16 KB
    const int t = threadIdx.x;
    const int row0 = blockIdx.x * 32;

    for (int i = t; i < 128 * 64; i += 256) Ws[i >> 6][i & 63] = W[i];
    for (int i = t; i < 32 * 128; i += 256) {
        int r = i >> 7, k = i & 127;
        int row = row0 + r;
        Xs[r][k] = (row < n) ? x[(size_t)row * 128 + k] : 0.0f;
    }
    __syncthreads();

    const int col = (t & 15) * 4;
    const int rg  = t >> 4;          // 0..15 -> rows rg*2, rg*2+1
    float4 a0 = {0.f, 0.f, 0.f, 0.f};
    float4 a1 = {0.f, 0.f, 0.f, 0.f};

    #pragma unroll 8
    for (int k = 0; k < 128; k++) {
        float4 w = *(const float4*)&Ws[k][col];
        float x0 = Xs[rg * 2 + 0][k];
        float x1 = Xs[rg * 2 + 1][k];
        a0.x += x0 * w.x; a0.y += x0 * w.y; a0.z += x0 * w.z; a0.w += x0 * w.w;
        a1.x += x1 * w.x; a1.y += x1 * w.y; a1.z += x1 * w.z; a1.w += x1 * w.w;
    }

    int row = row0 + rg * 2;
    #pragma unroll
    for (int rr = 0; rr < 2; rr++, row++) {
        if (row < n) {
            float s = d_dinv[row];
            float4 a = (rr == 0) ? a0 : a1;
            float4 o = {a.x * s, a.y * s, a.z * s, a.w * s};
            *(float4*)&d_g1  [(size_t)row * F1 + col] = o;
            *(float4*)&d_acc1[(size_t)row * F1 + col] = o;
        }
    }
}

// ---------------------------------------------------------------------------
// GEMM2: x1[i][k] = relu(acc1[i][k]*dinv[i] + b1[k]);
//        g2[i][j] = dinv[i] * sum_k x1[i][k] * W2[k][j]   (K=64, COLS=32)
__global__ __launch_bounds__(256) void gemm2_kernel(
    const float* __restrict__ W, const float* __restrict__ b1, int n)
{
    __shared__ __align__(16) float Ws[64][32];    // 8 KB
    __shared__ __align__(16) float Xs[64][64];    // 16 KB
    const int t = threadIdx.x;
    const int row0 = blockIdx.x * 64;

    for (int i = t; i < 64 * 32; i += 256) Ws[i >> 5][i & 31] = W[i];
    for (int i = t; i < 64 * 64; i += 256) {
        int r = i >> 6, k = i & 63;
        int row = row0 + r;
        float v = 0.0f;
        if (row < n)
            v = fmaxf(d_acc1[(size_t)row * F1 + k] * d_dinv[row] + b1[k], 0.0f);
        Xs[r][k] = v;
    }
    __syncthreads();

    const int col = (t & 7) * 4;
    const int rg  = t >> 3;          // 0..31 -> rows rg*2, rg*2+1
    float4 a0 = {0.f, 0.f, 0.f, 0.f};
    float4 a1 = {0.f, 0.f, 0.f, 0.f};

    #pragma unroll 8
    for (int k = 0; k < 64; k++) {
        float4 w = *(const float4*)&Ws[k][col];
        float x0 = Xs[rg * 2 + 0][k];
        float x1 = Xs[rg * 2 + 1][k];
        a0.x += x0 * w.x; a0.y += x0 * w.y; a0.z += x0 * w.z; a0.w += x0 * w.w;
        a1.x += x1 * w.x; a1.y += x1 * w.y; a1.z += x1 * w.z; a1.w += x1 * w.w;
    }

    int row = row0 + rg * 2;
    #pragma unroll
    for (int rr = 0; rr < 2; rr++, row++) {
        if (row < n) {
            float s = d_dinv[row];
            float4 a = (rr == 0) ? a0 : a1;
            float4 o = {a.x * s, a.y * s, a.z * s, a.w * s};
            *(float4*)&d_g2  [(size_t)row * F2 + col] = o;
            *(float4*)&d_acc2[(size_t)row * F2 + col] = o;
        }
    }
}

// ---------------------------------------------------------------------------
// Edge scatter layer 1: one warp per edge; acc1[dst][*] += g1[src][*].
__global__ __launch_bounds__(256) void scatter1_kernel(
    const void* __restrict__ ei, int E, int n)
{
    int w    = (blockIdx.x * blockDim.x + threadIdx.x) >> 5;
    int lane = threadIdx.x & 31;
    if (w >= E) return;
    int s = edge_at(ei, w, n);
    int d = edge_at(ei, (long long)E + w, n);
    const float* gp = d_g1   + (size_t)s * F1;
    float*       ap = d_acc1 + (size_t)d * F1;
    atomicAdd(ap + lane,      gp[lane]);
    atomicAdd(ap + 32 + lane, gp[32 + lane]);
}

// Edge scatter layer 2: one warp per edge; acc2[dst][*] += g2[src][*].
__global__ __launch_bounds__(256) void scatter2_kernel(
    const void* __restrict__ ei, int E, int n)
{
    int w    = (blockIdx.x * blockDim.x + threadIdx.x) >> 5;
    int lane = threadIdx.x & 31;
    if (w >= E) return;
    int s = edge_at(ei, w, n);
    int d = edge_at(ei, (long long)E + w, n);
    atomicAdd(d_acc2 + (size_t)d * F2 + lane, d_g2[(size_t)s * F2 + lane]);
}

// ---------------------------------------------------------------------------
__global__ void final_kernel(const float* __restrict__ b2,
                             float* __restrict__ out, int n)
{
    int i = blockIdx.x * blockDim.x + threadIdx.x;
    if (i < n * F2) {
        int row = i >> 5;   // F2 = 32
        int c   = i & 31;
        out[i] = fmaxf(d_acc2[i] * d_dinv[row] + b2[c], 0.0f);
    }
}

// ---------------------------------------------------------------------------
extern "C" void kernel_launch(void* const* d_in, const int* in_sizes, int n_in,
                              void* d_out, int out_size)
{
    const float* x  = (const float*)d_in[0];   // [N,128]
    const void*  ei = d_in[1];                 // [2,E], int32 or int64
    const float* W1 = (const float*)d_in[2];   // [128,64]
    const float* b1 = (const float*)d_in[3];   // [64]
    const float* W2 = (const float*)d_in[4];   // [64,32]
    const float* b2 = (const float*)d_in[5];   // [32]
    float*       out = (float*)d_out;

    const int N = in_sizes[0] / 128;
    const int E = in_sizes[1] / 2;

    // 0. dtype sniff
    sniff_kernel<<<1, 32>>>(ei);

    // 1. degree + dinv
    deg_init_kernel<<<(N + 255) / 256, 256>>>(N);
    deg_count_kernel<<<(E + 255) / 256, 256>>>(ei, E, N);
    dinv_kernel<<<(N + 255) / 256, 256>>>(N);

    // 2. layer 1: g1 = dinv*(x@W1), acc1 = g1 (self-loop), scatter
    gemm1_kernel<<<(N + 31) / 32, 256>>>(x, W1, N);
    scatter1_kernel<<<(E + 7) / 8, 256>>>(ei, E, N);   // 8 warps/block

    // 3. layer 2: fused relu(acc1*dinv+b1) -> GEMM -> g2, acc2 = g2, scatter
    gemm2_kernel<<<(N + 63) / 64, 256>>>(W2, b1, N);
    scatter2_kernel<<<(E + 7) / 8, 256>>>(ei, E, N);

    // 4. final epilogue
    final_kernel<<<(N * F2 + 255) / 256, 256>>>(b2, out, N);
}

// round 7
// speedup vs baseline: 1.0154x; 1.0154x over previous
#include <cuda_runtime.h>
#include <cuda_bf16.h>

// GCN 2-layer: N=50000 nodes, E=800000 edges, feats 128 -> 64 -> 32.
// out[d] = relu( dinv[d] * (sum_{e: dst=d} g[src_e] + g[d]) + b )
// where g = dinv ⊙ (x @ W).
// edge_index dtype (int32 vs int64) is sniffed at runtime on device.
// Scatter uses red.global.add.v4.f32 (sm_90+) — 4x fewer L2 atomic ops.

#define NMAX 50000
#define F1 64
#define F2 32

__device__ __align__(16) float d_deg [NMAX];
__device__ __align__(16) float d_dinv[NMAX];
__device__ __align__(16) float d_g1  [NMAX * F1];
__device__ __align__(16) float d_acc1[NMAX * F1];
__device__ __align__(16) float d_g2  [NMAX * F2];
__device__ __align__(16) float d_acc2[NMAX * F2];
__device__ int d_is64;

// ---------------------------------------------------------------------------
// Sniff edge_index dtype: int64 values < 2^31 have zero high halves at every
// odd 32-bit word; int32 random node ids in [0,50000) do not (P≈0).
__global__ void sniff_kernel(const void* ei) {
    if (threadIdx.x == 0 && blockIdx.x == 0) {
        const unsigned* w = (const unsigned*)ei;
        int all_zero = 1;
        for (int i = 0; i < 64; i++)
            if (w[2 * i + 1] != 0u) { all_zero = 0; break; }
        d_is64 = all_zero;
    }
}

__device__ __forceinline__ int edge_at(const void* ei, long long i, int n) {
    int v = d_is64 ? (int)((const long long*)ei)[i] : ((const int*)ei)[i];
    // defensive clamp: never produce a wild atomic address
    return min(max(v, 0), n - 1);
}

// ---------------------------------------------------------------------------
__global__ void deg_init_kernel(int n) {
    int i = blockIdx.x * blockDim.x + threadIdx.x;
    if (i < n) d_deg[i] = 1.0f;   // self-loop
}

__global__ void deg_count_kernel(const void* __restrict__ ei, int E, int n) {
    int e = blockIdx.x * blockDim.x + threadIdx.x;
    if (e < E) atomicAdd(&d_deg[edge_at(ei, (long long)E + e, n)], 1.0f);
}

__global__ void dinv_kernel(int n) {
    int i = blockIdx.x * blockDim.x + threadIdx.x;
    if (i < n) d_dinv[i] = rsqrtf(d_deg[i]);
}

// ---------------------------------------------------------------------------
// GEMM1: g1[i][j] = dinv[i] * sum_k x[i][k] * W1[k][j]   (K=128, COLS=64)
// Also writes acc1 = g1 (self-loop init).
__global__ __launch_bounds__(256) void gemm1_kernel(
    const float* __restrict__ x, const float* __restrict__ W, int n)
{
    __shared__ __align__(16) float Ws[128][64];   // 32 KB
    __shared__ __align__(16) float Xs[32][128];   // 16 KB
    const int t = threadIdx.x;
    const int row0 = blockIdx.x * 32;

    for (int i = t; i < 128 * 64; i += 256) Ws[i >> 6][i & 63] = W[i];
    for (int i = t; i < 32 * 128; i += 256) {
        int r = i >> 7, k = i & 127;
        int row = row0 + r;
        Xs[r][k] = (row < n) ? x[(size_t)row * 128 + k] : 0.0f;
    }
    __syncthreads();

    const int col = (t & 15) * 4;
    const int rg  = t >> 4;          // 0..15 -> rows rg*2, rg*2+1
    float4 a0 = {0.f, 0.f, 0.f, 0.f};
    float4 a1 = {0.f, 0.f, 0.f, 0.f};

    #pragma unroll 8
    for (int k = 0; k < 128; k++) {
        float4 w = *(const float4*)&Ws[k][col];
        float x0 = Xs[rg * 2 + 0][k];
        float x1 = Xs[rg * 2 + 1][k];
        a0.x += x0 * w.x; a0.y += x0 * w.y; a0.z += x0 * w.z; a0.w += x0 * w.w;
        a1.x += x1 * w.x; a1.y += x1 * w.y; a1.z += x1 * w.z; a1.w += x1 * w.w;
    }

    int row = row0 + rg * 2;
    #pragma unroll
    for (int rr = 0; rr < 2; rr++, row++) {
        if (row < n) {
            float s = d_dinv[row];
            float4 a = (rr == 0) ? a0 : a1;
            float4 o = {a.x * s, a.y * s, a.z * s, a.w * s};
            *(float4*)&d_g1  [(size_t)row * F1 + col] = o;
            *(float4*)&d_acc1[(size_t)row * F1 + col] = o;
        }
    }
}

// ---------------------------------------------------------------------------
// GEMM2: x1[i][k] = relu(acc1[i][k]*dinv[i] + b1[k]);
//        g2[i][j] = dinv[i] * sum_k x1[i][k] * W2[k][j]   (K=64, COLS=32)
__global__ __launch_bounds__(256) void gemm2_kernel(
    const float* __restrict__ W, const float* __restrict__ b1, int n)
{
    __shared__ __align__(16) float Ws[64][32];    // 8 KB
    __shared__ __align__(16) float Xs[64][64];    // 16 KB
    const int t = threadIdx.x;
    const int row0 = blockIdx.x * 64;

    for (int i = t; i < 64 * 32; i += 256) Ws[i >> 5][i & 31] = W[i];
    for (int i = t; i < 64 * 64; i += 256) {
        int r = i >> 6, k = i & 63;
        int row = row0 + r;
        float v = 0.0f;
        if (row < n)
            v = fmaxf(d_acc1[(size_t)row * F1 + k] * d_dinv[row] + b1[k], 0.0f);
        Xs[r][k] = v;
    }
    __syncthreads();

    const int col = (t & 7) * 4;
    const int rg  = t >> 3;          // 0..31 -> rows rg*2, rg*2+1
    float4 a0 = {0.f, 0.f, 0.f, 0.f};
    float4 a1 = {0.f, 0.f, 0.f, 0.f};

    #pragma unroll 8
    for (int k = 0; k < 64; k++) {
        float4 w = *(const float4*)&Ws[k][col];
        float x0 = Xs[rg * 2 + 0][k];
        float x1 = Xs[rg * 2 + 1][k];
        a0.x += x0 * w.x; a0.y += x0 * w.y; a0.z += x0 * w.z; a0.w += x0 * w.w;
        a1.x += x1 * w.x; a1.y += x1 * w.y; a1.z += x1 * w.z; a1.w += x1 * w.w;
    }

    int row = row0 + rg * 2;
    #pragma unroll
    for (int rr = 0; rr < 2; rr++, row++) {
        if (row < n) {
            float s = d_dinv[row];
            float4 a = (rr == 0) ? a0 : a1;
            float4 o = {a.x * s, a.y * s, a.z * s, a.w * s};
            *(float4*)&d_g2  [(size_t)row * F2 + col] = o;
            *(float4*)&d_acc2[(size_t)row * F2 + col] = o;
        }
    }
}

// ---------------------------------------------------------------------------
__device__ __forceinline__ void red_v4(float* ap, float4 v) {
    asm volatile("red.global.add.v4.f32 [%0], {%1, %2, %3, %4};"
                 :: "l"(ap), "f"(v.x), "f"(v.y), "f"(v.z), "f"(v.w)
                 : "memory");
}

// Edge scatter layer 1: one thread per (edge, float4 chunk); 16 chunks/edge.
__global__ __launch_bounds__(256) void scatter1_kernel(
    const void* __restrict__ ei, int E, int n)
{
    int i = blockIdx.x * blockDim.x + threadIdx.x;
    int e = i >> 4, c = i & 15;
    if (e >= E) return;
    int s = edge_at(ei, e, n);
    int d = edge_at(ei, (long long)E + e, n);
    float4 v = *(const float4*)(d_g1 + (size_t)s * F1 + c * 4);
    red_v4(d_acc1 + (size_t)d * F1 + c * 4, v);
}

// Edge scatter layer 2: one thread per (edge, float4 chunk); 8 chunks/edge.
__global__ __launch_bounds__(256) void scatter2_kernel(
    const void* __restrict__ ei, int E, int n)
{
    int i = blockIdx.x * blockDim.x + threadIdx.x;
    int e = i >> 3, c = i & 7;
    if (e >= E) return;
    int s = edge_at(ei, e, n);
    int d = edge_at(ei, (long long)E + e, n);
    float4 v = *(const float4*)(d_g2 + (size_t)s * F2 + c * 4);
    red_v4(d_acc2 + (size_t)d * F2 + c * 4, v);
}

// ---------------------------------------------------------------------------
__global__ void final_kernel(const float* __restrict__ b2,
                             float* __restrict__ out, int n)
{
    int i = blockIdx.x * blockDim.x + threadIdx.x;
    if (i < n * F2) {
        int row = i >> 5;   // F2 = 32
        int c   = i & 31;
        out[i] = fmaxf(d_acc2[i] * d_dinv[row] + b2[c], 0.0f);
    }
}

// ---------------------------------------------------------------------------
extern "C" void kernel_launch(void* const* d_in, const int* in_sizes, int n_in,
                              void* d_out, int out_size)
{
    const float* x  = (const float*)d_in[0];   // [N,128]
    const void*  ei = d_in[1];                 // [2,E], int32 or int64
    const float* W1 = (const float*)d_in[2];   // [128,64]
    const float* b1 = (const float*)d_in[3];   // [64]
    const float* W2 = (const float*)d_in[4];   // [64,32]
    const float* b2 = (const float*)d_in[5];   // [32]
    float*       out = (float*)d_out;

    const int N = in_sizes[0] / 128;
    const int E = in_sizes[1] / 2;

    // 0. dtype sniff
    sniff_kernel<<<1, 32>>>(ei);

    // 1. degree + dinv
    deg_init_kernel<<<(N + 255) / 256, 256>>>(N);
    deg_count_kernel<<<(E + 255) / 256, 256>>>(ei, E, N);
    dinv_kernel<<<(N + 255) / 256, 256>>>(N);

    // 2. layer 1: g1 = dinv*(x@W1), acc1 = g1 (self-loop), scatter
    gemm1_kernel<<<(N + 31) / 32, 256>>>(x, W1, N);
    {
        long long items = (long long)E * 16;
        scatter1_kernel<<<(unsigned)((items + 255) / 256), 256>>>(ei, E, N);
    }

    // 3. layer 2: fused relu(acc1*dinv+b1) -> GEMM -> g2, acc2 = g2, scatter
    gemm2_kernel<<<(N + 63) / 64, 256>>>(W2, b1, N);
    {
        long long items = (long long)E * 8;
        scatter2_kernel<<<(unsigned)((items + 255) / 256), 256>>>(ei, E, N);
    }

    // 4. final epilogue
    final_kernel<<<(N * F2 + 255) / 256, 256>>>(b2, out, N);
}

// round 8
// speedup vs baseline: 1.6845x; 1.6589x over previous
#include <cuda_runtime.h>
#include <cuda_bf16.h>

// GCN 2-layer: N=50000 nodes, E=800000 edges, feats 128 -> 64 -> 32.
// out[d] = relu( dinv[d] * (sum_{e: dst=d} g[src_e] + g[d]) + b )
// where g = dinv ⊙ (x @ W).
// R7: dst-CSR built on device; feature aggregation is a pure GATHER
// (no floating-point atomics — those were L2 atomic-lane bound).

#define NMAX 50000
#define EMAX 800000
#define F1 64
#define F2 32
#define SCAN_B 512

__device__ __align__(16) float d_dinv[NMAX];
__device__ __align__(16) float d_g1  [NMAX * F1];
__device__ __align__(16) float d_acc1[NMAX * F1];
__device__ __align__(16) float d_g2  [NMAX * F2];
__device__ int d_cnt [NMAX];          // in-degree (no self loop)
__device__ int d_off [NMAX];          // CSR row offsets (exclusive scan)
__device__ int d_cur [NMAX];          // fill cursors
__device__ int d_csr [EMAX];          // src ids grouped by dst
__device__ int d_bsum[(NMAX + SCAN_B - 1) / SCAN_B];
__device__ int d_is64;

// ---------------------------------------------------------------------------
// Sniff edge_index dtype: int64 values < 2^31 have zero high halves at every
// odd 32-bit word; int32 node ids in [0,50000) do not (P≈0).
__global__ void sniff_kernel(const void* ei) {
    if (threadIdx.x == 0 && blockIdx.x == 0) {
        const unsigned* w = (const unsigned*)ei;
        int all_zero = 1;
        for (int i = 0; i < 64; i++)
            if (w[2 * i + 1] != 0u) { all_zero = 0; break; }
        d_is64 = all_zero;
    }
}

__device__ __forceinline__ int edge_at(const void* ei, long long i, int n) {
    int v = d_is64 ? (int)((const long long*)ei)[i] : ((const int*)ei)[i];
    return min(max(v, 0), n - 1);   // defensive clamp
}

// ---------------------------------------------------------------------------
__global__ void cnt_init_kernel(int n) {
    int i = blockIdx.x * blockDim.x + threadIdx.x;
    if (i < n) d_cnt[i] = 0;
}

__global__ void cnt_count_kernel(const void* __restrict__ ei, int E, int n) {
    int e = blockIdx.x * blockDim.x + threadIdx.x;
    if (e < E) atomicAdd(&d_cnt[edge_at(ei, (long long)E + e, n)], 1);
}

__global__ void dinv_kernel(int n) {
    int i = blockIdx.x * blockDim.x + threadIdx.x;
    if (i < n) d_dinv[i] = rsqrtf(1.0f + (float)d_cnt[i]);
}

// Two-level exclusive scan of d_cnt -> d_off  ------------------------------
__global__ __launch_bounds__(SCAN_B) void scan1_kernel(int n) {
    __shared__ int sh[SCAN_B];
    int i = blockIdx.x * SCAN_B + threadIdx.x;
    int v = (i < n) ? d_cnt[i] : 0;
    sh[threadIdx.x] = v;
    __syncthreads();
    #pragma unroll
    for (int ofs = 1; ofs < SCAN_B; ofs <<= 1) {
        int t = (threadIdx.x >= ofs) ? sh[threadIdx.x - ofs] : 0;
        __syncthreads();
        sh[threadIdx.x] += t;
        __syncthreads();
    }
    if (i < n) d_off[i] = sh[threadIdx.x] - v;          // block-local exclusive
    if (threadIdx.x == SCAN_B - 1) d_bsum[blockIdx.x] = sh[SCAN_B - 1];
}

__global__ void scan2_kernel(int nb) {
    if (threadIdx.x == 0 && blockIdx.x == 0) {
        int acc = 0;
        for (int b = 0; b < nb; b++) { int t = d_bsum[b]; d_bsum[b] = acc; acc += t; }
    }
}

__global__ void scan3_kernel(int n) {
    int i = blockIdx.x * blockDim.x + threadIdx.x;
    if (i < n) {
        int o = d_off[i] + d_bsum[i / SCAN_B];
        d_off[i] = o;
        d_cur[i] = o;
    }
}

__global__ void fill_kernel(const void* __restrict__ ei, int E, int n) {
    int e = blockIdx.x * blockDim.x + threadIdx.x;
    if (e < E) {
        int s = edge_at(ei, e, n);
        int d = edge_at(ei, (long long)E + e, n);
        d_csr[atomicAdd(&d_cur[d], 1)] = s;
    }
}

// ---------------------------------------------------------------------------
// GEMM1: g1[i][j] = dinv[i] * sum_k x[i][k] * W1[k][j]   (K=128, COLS=64)
__global__ __launch_bounds__(256) void gemm1_kernel(
    const float* __restrict__ x, const float* __restrict__ W, int n)
{
    __shared__ __align__(16) float Ws[128][64];   // 32 KB
    __shared__ __align__(16) float Xs[32][128];   // 16 KB
    const int t = threadIdx.x;
    const int row0 = blockIdx.x * 32;

    for (int i = t; i < 128 * 64; i += 256) Ws[i >> 6][i & 63] = W[i];
    for (int i = t; i < 32 * 128; i += 256) {
        int r = i >> 7, k = i & 127;
        int row = row0 + r;
        Xs[r][k] = (row < n) ? x[(size_t)row * 128 + k] : 0.0f;
    }
    __syncthreads();

    const int col = (t & 15) * 4;
    const int rg  = t >> 4;
    float4 a0 = {0.f, 0.f, 0.f, 0.f};
    float4 a1 = {0.f, 0.f, 0.f, 0.f};

    #pragma unroll 8
    for (int k = 0; k < 128; k++) {
        float4 w = *(const float4*)&Ws[k][col];
        float x0 = Xs[rg * 2 + 0][k];
        float x1 = Xs[rg * 2 + 1][k];
        a0.x += x0 * w.x; a0.y += x0 * w.y; a0.z += x0 * w.z; a0.w += x0 * w.w;
        a1.x += x1 * w.x; a1.y += x1 * w.y; a1.z += x1 * w.z; a1.w += x1 * w.w;
    }

    int row = row0 + rg * 2;
    #pragma unroll
    for (int rr = 0; rr < 2; rr++, row++) {
        if (row < n) {
            float s = d_dinv[row];
            float4 a = (rr == 0) ? a0 : a1;
            float4 o = {a.x * s, a.y * s, a.z * s, a.w * s};
            *(float4*)&d_g1[(size_t)row * F1 + col] = o;
        }
    }
}

// ---------------------------------------------------------------------------
// Gather layer 1: one warp per dst node; acc1[d] = g1[d] + sum g1[src].
__global__ __launch_bounds__(256) void gather1_kernel(int n)
{
    int w    = (blockIdx.x * blockDim.x + threadIdx.x) >> 5;
    int lane = threadIdx.x & 31;
    if (w >= n) return;
    int beg = d_off[w];
    int end = beg + d_cnt[w];
    float a0 = d_g1[(size_t)w * F1 + lane];        // self loop
    float a1 = d_g1[(size_t)w * F1 + 32 + lane];
    int j = beg;
    for (; j + 1 < end; j += 2) {
        int s0 = d_csr[j], s1 = d_csr[j + 1];
        const float* p0 = d_g1 + (size_t)s0 * F1;
        const float* p1 = d_g1 + (size_t)s1 * F1;
        float v0 = p0[lane], v1 = p0[32 + lane];
        float v2 = p1[lane], v3 = p1[32 + lane];
        a0 += v0; a1 += v1; a0 += v2; a1 += v3;
    }
    if (j < end) {
        const float* p = d_g1 + (size_t)d_csr[j] * F1;
        a0 += p[lane]; a1 += p[32 + lane];
    }
    d_acc1[(size_t)w * F1 + lane]      = a0;
    d_acc1[(size_t)w * F1 + 32 + lane] = a1;
}

// ---------------------------------------------------------------------------
// GEMM2: x1[i][k] = relu(acc1[i][k]*dinv[i] + b1[k]);
//        g2[i][j] = dinv[i] * sum_k x1[i][k] * W2[k][j]   (K=64, COLS=32)
__global__ __launch_bounds__(256) void gemm2_kernel(
    const float* __restrict__ W, const float* __restrict__ b1, int n)
{
    __shared__ __align__(16) float Ws[64][32];    // 8 KB
    __shared__ __align__(16) float Xs[64][64];    // 16 KB
    const int t = threadIdx.x;
    const int row0 = blockIdx.x * 64;

    for (int i = t; i < 64 * 32; i += 256) Ws[i >> 5][i & 31] = W[i];
    for (int i = t; i < 64 * 64; i += 256) {
        int r = i >> 6, k = i & 63;
        int row = row0 + r;
        float v = 0.0f;
        if (row < n)
            v = fmaxf(d_acc1[(size_t)row * F1 + k] * d_dinv[row] + b1[k], 0.0f);
        Xs[r][k] = v;
    }
    __syncthreads();

    const int col = (t & 7) * 4;
    const int rg  = t >> 3;
    float4 a0 = {0.f, 0.f, 0.f, 0.f};
    float4 a1 = {0.f, 0.f, 0.f, 0.f};

    #pragma unroll 8
    for (int k = 0; k < 64; k++) {
        float4 w = *(const float4*)&Ws[k][col];
        float x0 = Xs[rg * 2 + 0][k];
        float x1 = Xs[rg * 2 + 1][k];
        a0.x += x0 * w.x; a0.y += x0 * w.y; a0.z += x0 * w.z; a0.w += x0 * w.w;
        a1.x += x1 * w.x; a1.y += x1 * w.y; a1.z += x1 * w.z; a1.w += x1 * w.w;
    }

    int row = row0 + rg * 2;
    #pragma unroll
    for (int rr = 0; rr < 2; rr++, row++) {
        if (row < n) {
            float s = d_dinv[row];
            float4 a = (rr == 0) ? a0 : a1;
            float4 o = {a.x * s, a.y * s, a.z * s, a.w * s};
            *(float4*)&d_g2[(size_t)row * F2 + col] = o;
        }
    }
}

// ---------------------------------------------------------------------------
// Gather layer 2 + final epilogue fused:
//   out[d] = relu( dinv[d] * (g2[d] + sum g2[src]) + b2 )
__global__ __launch_bounds__(256) void gather2_kernel(
    const float* __restrict__ b2, float* __restrict__ out, int n)
{
    int w    = (blockIdx.x * blockDim.x + threadIdx.x) >> 5;
    int lane = threadIdx.x & 31;
    if (w >= n) return;
    int beg = d_off[w];
    int end = beg + d_cnt[w];
    float a = d_g2[(size_t)w * F2 + lane];         // self loop
    int j = beg;
    for (; j + 3 < end; j += 4) {
        int s0 = d_csr[j], s1 = d_csr[j + 1], s2 = d_csr[j + 2], s3 = d_csr[j + 3];
        float v0 = d_g2[(size_t)s0 * F2 + lane];
        float v1 = d_g2[(size_t)s1 * F2 + lane];
        float v2 = d_g2[(size_t)s2 * F2 + lane];
        float v3 = d_g2[(size_t)s3 * F2 + lane];
        a += v0; a += v1; a += v2; a += v3;
    }
    for (; j < end; j++)
        a += d_g2[(size_t)d_csr[j] * F2 + lane];
    out[(size_t)w * F2 + lane] = fmaxf(a * d_dinv[w] + b2[lane], 0.0f);
}

// ---------------------------------------------------------------------------
extern "C" void kernel_launch(void* const* d_in, const int* in_sizes, int n_in,
                              void* d_out, int out_size)
{
    const float* x  = (const float*)d_in[0];   // [N,128]
    const void*  ei = d_in[1];                 // [2,E], int32 or int64
    const float* W1 = (const float*)d_in[2];   // [128,64]
    const float* b1 = (const float*)d_in[3];   // [64]
    const float* W2 = (const float*)d_in[4];   // [64,32]
    const float* b2 = (const float*)d_in[5];   // [32]
    float*       out = (float*)d_out;

    const int N = in_sizes[0] / 128;
    const int E = in_sizes[1] / 2;
    const int NB = (N + SCAN_B - 1) / SCAN_B;

    // 0. dtype sniff
    sniff_kernel<<<1, 32>>>(ei);

    // 1. in-degree counts + dinv
    cnt_init_kernel<<<(N + 255) / 256, 256>>>(N);
    cnt_count_kernel<<<(E + 255) / 256, 256>>>(ei, E, N);
    dinv_kernel<<<(N + 255) / 256, 256>>>(N);

    // 2. CSR build: scan + fill
    scan1_kernel<<<NB, SCAN_B>>>(N);
    scan2_kernel<<<1, 32>>>(NB);
    scan3_kernel<<<(N + 255) / 256, 256>>>(N);
    fill_kernel<<<(E + 255) / 256, 256>>>(ei, E, N);

    // 3. layer 1: g1 = dinv*(x@W1), gather (self-loop folded in)
    gemm1_kernel<<<(N + 31) / 32, 256>>>(x, W1, N);
    gather1_kernel<<<(N + 7) / 8, 256>>>(N);       // 8 warps/block

    // 4. layer 2: fused relu(acc1*dinv+b1) -> GEMM -> g2, gather + epilogue
    gemm2_kernel<<<(N + 63) / 64, 256>>>(W2, b1, N);
    gather2_kernel<<<(N + 7) / 8, 256>>>(b2, out, N);
}